// round 8
// baseline (speedup 1.0000x reference)
#include <cuda_runtime.h>
#include <stdint.h>

// MyDropout: out = x * mask; mask = JAX partitionable-threefry dropout
// (seed 42, p=0.1), columns < 64 zeroed. x: [16384, 4096] f32, N = 67108864.
//
//   bits(i) = o0 ^ o1, (o0,o1) = threefry2x32(key=(0,42), ctr=(0,i))
//   keep  <=>  bits < 0xE6666600
//
// Rotates as WIDENING MULTIPLY: w = v * 2^r -> {lo = v<<r, hi = v>>(32-r)},
// rot(v,r) = lo|hi. The multipliers 2^r are passed as KERNEL PARAMETERS so
// ptxas cannot strength-reduce the mul.wide.u32 back into SHF (round-7 SASS
// proved it folds compile-time pow2 multipliers). IMAD.WIDE lands on the fma
// pipe; (lo|hi)^x0 is one LOP3 on the alu pipe. Round cost rebalances from
// 2.5-alu/0.5-fma to 1.5-alu/1.5-fma, lifting the 93.6% alu-pipe ceiling.

__device__ __forceinline__ uint32_t rotm(uint32_t v, uint32_t m, uint32_t x0) {
    uint64_t w = (uint64_t)v * (uint64_t)m;   // IMAD.WIDE.U32 (fma pipe), m opaque
    return (((uint32_t)w) | ((uint32_t)(w >> 32))) ^ x0;  // single LOP3 (alu)
}

#define RND(m) do { x0 += x1; x1 = rotm(x1, (m), x0); } while (0)

__device__ __forceinline__ uint32_t tf_bits(uint32_t i, uint4 ma, uint4 mb) {
    const uint32_t k1 = 42u;
    const uint32_t k2 = 0x1BD11BF0u;   // 0x1BD11BDA ^ 0 ^ 42

    uint32_t x1 = i + k1;      // ctr_lo + k1
    uint32_t x0 = x1;          // round 1 add: x0 = (ctr_hi + k0) + x1 = x1 (k0 = 0)
    x1 = rotm(x1, ma.x, x0);   // r=13, rest of round 1
    RND(ma.y); RND(ma.z); RND(ma.w);          // 15, 26, 6
    x0 += k1; x1 += k2 + 1u;
    RND(mb.x); RND(mb.y); RND(mb.z); RND(mb.w);  // 17, 29, 16, 24
    x0 += k2; x1 += 2u;                          // + k0(=0) + 2
    RND(ma.x); RND(ma.y); RND(ma.z); RND(ma.w);  // 13, 15, 26, 6
    x0 += 0u; x1 += k1 + 3u;
    RND(mb.x); RND(mb.y); RND(mb.z); RND(mb.w);  // 17, 29, 16, 24
    x0 += k1; x1 += k2 + 4u;
    RND(ma.x); RND(ma.y); RND(ma.z); RND(ma.w);  // 13, 15, 26, 6
    x0 += k2; x1 += 5u;                          // + k0(=0) + 5
    return x0 ^ x1;            // partitionable 32-bit output
}

__global__ __launch_bounds__(256) void mydropout_kernel(
    const float4* __restrict__ x, float4* __restrict__ out,
    uint4 ma, uint4 mb) {
    const uint32_t KEEP_LT = 0xE6666600u;   // bits < this  <=>  keep (u < 0.9f)
    const float scale = (float)(1.0 / 0.9);

    uint32_t tid = blockIdx.x * blockDim.x + threadIdx.x;  // one float4 / thread
    uint32_t g = tid << 2;                                 // element index
    uint32_t col = g & 4095u;                              // column (row width 4096)

    if (col < 64u) {
        // K=64 leading columns zeroed; float4-aligned, whole vector is zero.
        out[tid] = make_float4(0.f, 0.f, 0.f, 0.f);
        return;
    }

    float4 a = x[tid];

    uint32_t b0 = tf_bits(g + 0u, ma, mb);
    uint32_t b1 = tf_bits(g + 1u, ma, mb);
    uint32_t b2 = tf_bits(g + 2u, ma, mb);
    uint32_t b3 = tf_bits(g + 3u, ma, mb);

    float4 r;
    r.x = a.x * ((b0 < KEEP_LT) ? scale : 0.f);
    r.y = a.y * ((b1 < KEEP_LT) ? scale : 0.f);
    r.z = a.z * ((b2 < KEEP_LT) ? scale : 0.f);
    r.w = a.w * ((b3 < KEEP_LT) ? scale : 0.f);

    out[tid] = r;
}

extern "C" void kernel_launch(void* const* d_in, const int* in_sizes, int n_in,
                              void* d_out, int out_size) {
    const float4* x = (const float4*)d_in[0];
    float4* out = (float4*)d_out;
    // Rotation multipliers 2^r as runtime kernel args (opaque to ptxas).
    uint4 ma = make_uint4(1u << 13, 1u << 15, 1u << 26, 1u << 6);
    uint4 mb = make_uint4(1u << 17, 1u << 29, 1u << 16, 1u << 24);
    const int threads = 256;
    const int blocks = 16777216 / threads;  // N/4 threads
    mydropout_kernel<<<blocks, threads>>>(x, out, ma, mb);
}

// round 9
// speedup vs baseline: 1.2914x; 1.2914x over previous
#include <cuda_runtime.h>
#include <stdint.h>

// MyDropout: out = x * mask; mask = JAX partitionable-threefry dropout
// (seed 42, p=0.1), columns < 64 zeroed. x: [16384, 4096] f32, N = 67108864.
//
//   bits(i) = o0 ^ o1, (o0,o1) = threefry2x32(key=(0,42), ctr=(0,i))
//   keep  <=>  bits < 0xE6666600
//
// Pipe strategy (from round-7/8 evidence): SHF and LOP3 are alu-pipe-only and
// irreducible (2 alu/round). The ADDS are the movable work: written as
// a*one + b with `one` an opaque kernel parameter, they MUST compile to IMAD
// (fma pipe). This cuts alu work/elem ~52 -> ~42 without the IMAD.WIDE
// register-pair/latency poison that regressed round 8 (167 -> 207 us).

#define TF_ROT(x, r) (((x) << (r)) | ((x) >> (32 - (r))))

// Add forced onto the fma pipe: IMAD Rd, Ra, one, Rb (one is opaque to ptxas).
#define FADDU(a, b) ((a) * one + (b))

// One threefry round: add on fma pipe, SHF+LOP3 on alu pipe.
#define RND(r) do { x0 = FADDU(x0, x1); x1 = TF_ROT(x1, r) ^ x0; } while (0)

__device__ __forceinline__ uint32_t tf_bits(uint32_t i, uint32_t one) {
    const uint32_t k1 = 42u;
    const uint32_t k2 = 0x1BD11BF0u;   // 0x1BD11BDA ^ 0 ^ 42

    uint32_t x1 = FADDU(i, k1);        // ctr_lo + k1  (IMAD)
    uint32_t x0 = x1;                  // round-1 add: x0 = 0 + x1
    x1 = TF_ROT(x1, 13) ^ x0;          // rest of round 1
    RND(15); RND(26); RND(6);
    x0 = FADDU(x0, k1); x1 = FADDU(x1, k2 + 1u);
    RND(17); RND(29); RND(16); RND(24);
    x0 = FADDU(x0, k2); x1 = FADDU(x1, 2u);          // k0 = 0
    RND(13); RND(15); RND(26); RND(6);
    x1 = FADDU(x1, k1 + 3u);                          // x0 += k0 is a no-op
    RND(17); RND(29); RND(16); RND(24);
    x0 = FADDU(x0, k1); x1 = FADDU(x1, k2 + 4u);
    RND(13); RND(15); RND(26); RND(6);
    x0 = FADDU(x0, k2); x1 = FADDU(x1, 5u);          // k0 = 0
    return x0 ^ x1;                    // partitionable 32-bit output
}

__global__ __launch_bounds__(256) void mydropout_kernel(
    const float4* __restrict__ x, float4* __restrict__ out, uint32_t one) {
    const uint32_t KEEP_LT = 0xE6666600u;   // bits < this  <=>  keep (u < 0.9f)
    const float scale = (float)(1.0 / 0.9);

    uint32_t tid = blockIdx.x * blockDim.x + threadIdx.x;  // one float4 / thread
    uint32_t g = tid << 2;                                 // element index
    uint32_t col = g & 4095u;                              // column (row width 4096)

    if (col < 64u) {
        // K=64 leading columns zeroed; float4-aligned, whole vector is zero.
        out[tid] = make_float4(0.f, 0.f, 0.f, 0.f);
        return;
    }

    float4 a = x[tid];

    uint32_t b0 = tf_bits(g + 0u, one);
    uint32_t b1 = tf_bits(g + 1u, one);
    uint32_t b2 = tf_bits(g + 2u, one);
    uint32_t b3 = tf_bits(g + 3u, one);

    float4 r;
    r.x = a.x * ((b0 < KEEP_LT) ? scale : 0.f);
    r.y = a.y * ((b1 < KEEP_LT) ? scale : 0.f);
    r.z = a.z * ((b2 < KEEP_LT) ? scale : 0.f);
    r.w = a.w * ((b3 < KEEP_LT) ? scale : 0.f);

    out[tid] = r;
}

extern "C" void kernel_launch(void* const* d_in, const int* in_sizes, int n_in,
                              void* d_out, int out_size) {
    const float4* x = (const float4*)d_in[0];
    float4* out = (float4*)d_out;
    const int threads = 256;
    const int blocks = 16777216 / threads;  // N/4 threads
    mydropout_kernel<<<blocks, threads>>>(x, out, 1u /* opaque multiplier */);
}